// round 2
// baseline (speedup 1.0000x reference)
#include <cuda_runtime.h>

// Problem constants (fixed by the dataset)
#define NN 20000
#define BB 64
#define EE 1280000

// Scratch (allocation-free requirement -> __device__ globals)
__device__ float g_xT[NN * BB];   // x transposed to [N, B]
__device__ float g_acc[NN * BB];  // neighbor-sum accumulator [N, B]

// ---------------------------------------------------------------------------
// Kernel 1: transpose x [B,N] -> xT [N,B]; also zero the accumulator.
// One block handles a tile of 64 nodes x 64 batch. 256 threads.
// ---------------------------------------------------------------------------
__global__ void k_transpose(const float* __restrict__ x) {
    __shared__ float tile[64][65];
    const int n0 = blockIdx.x * 64;

    // Load: consecutive threads -> consecutive n (coalesced along x rows)
    #pragma unroll
    for (int i = threadIdx.x; i < 64 * 64; i += 256) {
        int bb = i >> 6;       // batch
        int nl = i & 63;       // node within tile
        int n = n0 + nl;
        tile[nl][bb] = (n < NN) ? x[bb * NN + n] : 0.0f;
    }
    __syncthreads();

    // Store: consecutive threads -> consecutive b (coalesced 256B segments)
    #pragma unroll
    for (int i = threadIdx.x; i < 64 * 64; i += 256) {
        int nl = i >> 6;
        int bb = i & 63;
        int n = n0 + nl;
        if (n < NN) {
            g_xT[n * 64 + bb]  = tile[nl][bb];
            g_acc[n * 64 + bb] = 0.0f;
        }
    }
}

// ---------------------------------------------------------------------------
// Kernel 2: per-edge scatter. 16 lanes per edge, each lane owns one float4
// of the 64-float feature vector. Scalar edge data loads are broadcast hits.
// red.global.add.v4.f32 = vectorized no-return atomic (sm_90+).
// ---------------------------------------------------------------------------
__global__ void k_edges(const float* __restrict__ adj,
                        const float* __restrict__ w,
                        const int* __restrict__ src,
                        const int* __restrict__ dst) {
    long long t = (long long)blockIdx.x * blockDim.x + threadIdx.x;
    int e = (int)(t >> 4);
    int j = (int)(t & 15);
    if (e >= EE) return;

    float c = __ldg(&adj[e]) * __ldg(&w[e]);
    int s = __ldg(&src[e]);
    int d = __ldg(&dst[e]);

    const float4* xv4 = reinterpret_cast<const float4*>(g_xT + (long long)s * 64);
    float4 xv = xv4[j];

    float4 r;
    r.x = xv.x * c; r.y = xv.y * c; r.z = xv.z * c; r.w = xv.w * c;

    float* ap = g_acc + (long long)d * 64 + j * 4;
    asm volatile("red.global.add.v4.f32 [%0], {%1,%2,%3,%4};"
                 :: "l"(ap), "f"(r.x), "f"(r.y), "f"(r.z), "f"(r.w)
                 : "memory");
}

// ---------------------------------------------------------------------------
// Kernel 3: epilogue. out[b,n] = relu(acc[n,b] * x[0,n]*self_w[n] + bias[n]).
// Transpose back through smem; per-node terms staged in smem once per block.
// ---------------------------------------------------------------------------
__global__ void k_epilogue(const float* __restrict__ x,
                           const float* __restrict__ self_w,
                           const float* __restrict__ bias,
                           float* __restrict__ out) {
    __shared__ float tile[64][65];
    __shared__ float sl[64];
    __shared__ float bs[64];
    const int n0 = blockIdx.x * 64;

    if (threadIdx.x < 64) {
        int n = n0 + threadIdx.x;
        if (n < NN) {
            sl[threadIdx.x] = x[n] * self_w[n];   // x row 0 == x[0*NN + n]
            bs[threadIdx.x] = bias[n];
        }
    }
    // Load acc: consecutive threads -> consecutive b (coalesced)
    #pragma unroll
    for (int i = threadIdx.x; i < 64 * 64; i += 256) {
        int nl = i >> 6;
        int bb = i & 63;
        int n = n0 + nl;
        tile[nl][bb] = (n < NN) ? g_acc[n * 64 + bb] : 0.0f;
    }
    __syncthreads();

    // Store out: consecutive threads -> consecutive n (coalesced)
    #pragma unroll
    for (int i = threadIdx.x; i < 64 * 64; i += 256) {
        int bb = i >> 6;
        int nl = i & 63;
        int n = n0 + nl;
        if (n < NN) {
            float v = fmaf(tile[nl][bb], sl[nl], bs[nl]);
            out[(long long)bb * NN + n] = fmaxf(v, 0.0f);
        }
    }
}

// ---------------------------------------------------------------------------
// Launch. Input order per metadata: x, adj_values, w, self_w, b, src, dst.
// ---------------------------------------------------------------------------
extern "C" void kernel_launch(void* const* d_in, const int* in_sizes, int n_in,
                              void* d_out, int out_size) {
    const float* x      = (const float*)d_in[0];
    const float* adj    = (const float*)d_in[1];
    const float* w      = (const float*)d_in[2];
    const float* self_w = (const float*)d_in[3];
    const float* bias   = (const float*)d_in[4];
    const int*   src    = (const int*)d_in[5];
    const int*   dst    = (const int*)d_in[6];
    float* out = (float*)d_out;

    const int n_tiles = (NN + 63) / 64;  // 313

    k_transpose<<<n_tiles, 256>>>(x);

    const long long edge_threads = (long long)EE * 16;
    const int edge_blocks = (int)((edge_threads + 255) / 256);  // 80000
    k_edges<<<edge_blocks, 256>>>(adj, w, src, dst);

    k_epilogue<<<n_tiles, 256>>>(x, self_w, bias, out);
}